// round 1
// baseline (speedup 1.0000x reference)
#include <cuda_runtime.h>
#include <math.h>

#define NN 4096
#define DD 64
#define HH 4
#define NSTEPS 4

// ---------------- scratch (__device__ globals; no allocations) ----------------
__device__ float    g_h   [(size_t)HH * NN * DD];   // projected features per head
__device__ float    g_hn  [(size_t)HH * NN * DD];   // row-normalized
__device__ float    g_sim [(size_t)HH * NN * NN];   // 268 MB sim scratch
__device__ unsigned g_rowmax[HH * NN];              // ordered-int encoded masked row max
__device__ float    g_hmean [HH * DD];              // per-head column mean of h (fallback)
__device__ float    g_xbuf[2][NN * DD];             // feature ping-pong

// ordered-int encoding for float atomicMax
__device__ __forceinline__ unsigned f2ord(float f) {
    unsigned u = __float_as_uint(f);
    return (u & 0x80000000u) ? ~u : (u | 0x80000000u);
}
__device__ __forceinline__ float ord2f(unsigned u) {
    u = (u & 0x80000000u) ? (u & 0x7FFFFFFFu) : ~u;
    return __uint_as_float(u);
}
#define ORD_NEG_INF 0x007FFFFFu   // f2ord(-inf)

// ---------------- per-step init: zero next-x, hmean, reset rowmax ----------------
__global__ void k_init(int step, float* dout) {
    float* nxt = (step == NSTEPS - 1) ? dout : g_xbuf[step & 1];
    int i = blockIdx.x * blockDim.x + threadIdx.x;
    if (i < NN * DD) nxt[i] = 0.f;
    if (i < HH * NN) g_rowmax[i] = ORD_NEG_INF;
    if (i < HH * DD) g_hmean[i] = 0.f;
}

// ---------------- projection + row-normalize + column mean ----------------
// grid (NN/64, HH), block 256. Each block: 64 rows x 64 cols for one head.
__global__ void k_project(int step, const float* __restrict__ feat,
                          const float* __restrict__ Ws) {
    const float* x = (step == 0) ? feat : g_xbuf[(step + 1) & 1];
    int h = blockIdx.y;
    const float* W = Ws + ((size_t)step * HH + h) * DD * DD;
    int row0 = blockIdx.x * 64;

    __shared__ float sW[DD * DD];     // 16 KB
    __shared__ float sX[64 * DD];     // 16 KB
    __shared__ float sPart[8][16];

    for (int i = threadIdx.x; i < DD * DD; i += 256) sW[i] = W[i];
    for (int i = threadIdx.x; i < 64 * DD; i += 256) sX[i] = x[(size_t)row0 * DD + i];
    __syncthreads();

    int tx = threadIdx.x & 63;   // output column e
    int ty = threadIdx.x >> 6;   // 0..3 ; rows r = ty + 4*i

    float hv[16];
    #pragma unroll
    for (int i = 0; i < 16; i++) {
        int r = ty + i * 4;
        float acc = 0.f;
        #pragma unroll
        for (int d = 0; d < DD; d++) acc = fmaf(sX[r * DD + d], sW[d * DD + tx], acc);
        hv[i] = acc;
    }

    // row sum-of-squares: reduce over the 64 threads of this ty-group (2 warps)
    float ss[16];
    #pragma unroll
    for (int i = 0; i < 16; i++) ss[i] = hv[i] * hv[i];
    #pragma unroll
    for (int o = 16; o > 0; o >>= 1) {
        #pragma unroll
        for (int i = 0; i < 16; i++) ss[i] += __shfl_xor_sync(0xffffffffu, ss[i], o);
    }
    int w = threadIdx.x >> 5;  // warp id 0..7 ; ty-group = warps {2*ty, 2*ty+1}
    if ((threadIdx.x & 31) == 0) {
        #pragma unroll
        for (int i = 0; i < 16; i++) sPart[w][i] = ss[i];
    }
    __syncthreads();

    float msum = 0.f;
    #pragma unroll
    for (int i = 0; i < 16; i++) {
        int r = ty + i * 4;
        float nsq = sPart[ty * 2][i] + sPart[ty * 2 + 1][i];
        float rn = 1.f / (sqrtf(nsq) + 1e-12f);
        size_t idx = ((size_t)h * NN + row0 + r) * DD + tx;
        g_h[idx]  = hv[i];
        g_hn[idx] = hv[i] * rn;
        msum += hv[i];
    }
    atomicAdd(&g_hmean[h * DD + tx], msum * (1.0f / NN));
}

// ---------------- sim = hn @ hn^T / TEMP ; store + masked row max ----------------
// grid (32, 32, HH) = 128x128 tiles, block 256 (16x16, 8x8 micro), K=64 one shot.
__global__ void k_sim(int step, const int* __restrict__ adjf) {
    extern __shared__ float sm[];
    float* sA = sm;               // [64][128] k-major
    float* sB = sm + 64 * 128;    // [64][128] k-major
    const int* adj = adjf + (size_t)step * NN * NN;
    int h  = blockIdx.z;
    int rb = blockIdx.y * 128, cb = blockIdx.x * 128;
    const float* base = g_hn + (size_t)h * NN * DD;

    #pragma unroll
    for (int t = 0; t < 8; t++) {
        int idx = threadIdx.x + t * 256;       // 0..2047
        int r = idx >> 4;
        int k = (idx & 15) << 2;
        float4 va = *(const float4*)&base[(size_t)(rb + r) * DD + k];
        sA[(k + 0) * 128 + r] = va.x; sA[(k + 1) * 128 + r] = va.y;
        sA[(k + 2) * 128 + r] = va.z; sA[(k + 3) * 128 + r] = va.w;
        float4 vb = *(const float4*)&base[(size_t)(cb + r) * DD + k];
        sB[(k + 0) * 128 + r] = vb.x; sB[(k + 1) * 128 + r] = vb.y;
        sB[(k + 2) * 128 + r] = vb.z; sB[(k + 3) * 128 + r] = vb.w;
    }
    __syncthreads();

    int tx = threadIdx.x & 15, ty = threadIdx.x >> 4;
    float acc[8][8];
    #pragma unroll
    for (int i = 0; i < 8; i++)
        #pragma unroll
        for (int j = 0; j < 8; j++) acc[i][j] = 0.f;

    #pragma unroll
    for (int k = 0; k < 64; k++) {
        float4 a0 = *(const float4*)&sA[k * 128 + ty * 4];
        float4 a1 = *(const float4*)&sA[k * 128 + ty * 4 + 64];
        float4 b0 = *(const float4*)&sB[k * 128 + tx * 4];
        float4 b1 = *(const float4*)&sB[k * 128 + tx * 4 + 64];
        float a[8] = {a0.x, a0.y, a0.z, a0.w, a1.x, a1.y, a1.z, a1.w};
        float b[8] = {b0.x, b0.y, b0.z, b0.w, b1.x, b1.y, b1.z, b1.w};
        #pragma unroll
        for (int i = 0; i < 8; i++)
            #pragma unroll
            for (int j = 0; j < 8; j++) acc[i][j] = fmaf(a[i], b[j], acc[i][j]);
    }

    // epilogue: scale by 1/TEMP = 5, store sim, masked row max
    float* simbase = g_sim + (size_t)h * NN * NN;
    float rmax[8];
    #pragma unroll
    for (int i = 0; i < 8; i++) rmax[i] = -INFINITY;

    #pragma unroll
    for (int i = 0; i < 8; i++) {
        int lr = ty * 4 + (i & 3) + ((i >> 2) << 6);
        int gr = rb + lr;
        float4 s0 = make_float4(acc[i][0] * 5.f, acc[i][1] * 5.f, acc[i][2] * 5.f, acc[i][3] * 5.f);
        float4 s1 = make_float4(acc[i][4] * 5.f, acc[i][5] * 5.f, acc[i][6] * 5.f, acc[i][7] * 5.f);
        size_t o0 = (size_t)gr * NN + cb + tx * 4;
        *(float4*)&simbase[o0]      = s0;
        *(float4*)&simbase[o0 + 64] = s1;
        int4 m0 = *(const int4*)&adj[o0];
        int4 m1 = *(const int4*)&adj[o0 + 64];
        if (m0.x > 0) rmax[i] = fmaxf(rmax[i], s0.x);
        if (m0.y > 0) rmax[i] = fmaxf(rmax[i], s0.y);
        if (m0.z > 0) rmax[i] = fmaxf(rmax[i], s0.z);
        if (m0.w > 0) rmax[i] = fmaxf(rmax[i], s0.w);
        if (m1.x > 0) rmax[i] = fmaxf(rmax[i], s1.x);
        if (m1.y > 0) rmax[i] = fmaxf(rmax[i], s1.y);
        if (m1.z > 0) rmax[i] = fmaxf(rmax[i], s1.z);
        if (m1.w > 0) rmax[i] = fmaxf(rmax[i], s1.w);
    }

    __syncthreads();
    unsigned* smax = (unsigned*)sA;
    if (threadIdx.x < 128) smax[threadIdx.x] = ORD_NEG_INF;
    __syncthreads();
    #pragma unroll
    for (int i = 0; i < 8; i++) {
        int lr = ty * 4 + (i & 3) + ((i >> 2) << 6);
        atomicMax(&smax[lr], f2ord(rmax[i]));
    }
    __syncthreads();
    if (threadIdx.x < 128)
        atomicMax(&g_rowmax[h * NN + rb + threadIdx.x], smax[threadIdx.x]);
}

// ---------------- keep + exp + P@h + elu + head mean ----------------
// grid (NN/32, HH): 32-row tiles, loop over 128-col tiles. block 256.
#define SP_STRIDE 132
__global__ void k_attn(int step, const int* __restrict__ adjf, float* __restrict__ doutp) {
    extern __shared__ float sm[];
    float* sP   = sm;                          // [32][SP_STRIDE]
    float* sHt  = sm + 32 * SP_STRIDE;         // [128][64]
    float* sRM  = sHt + 128 * 64;              // [32]
    float* sDen = sRM + 32;                    // [32]

    const int* adj = adjf + (size_t)step * NN * NN;
    float* out = (step == NSTEPS - 1) ? doutp : g_xbuf[step & 1];
    int h  = blockIdx.y;
    int rb = blockIdx.x * 32;

    if (threadIdx.x < 32)
        sRM[threadIdx.x] = ord2f(g_rowmax[h * NN + rb + threadIdx.x]);

    int tx = threadIdx.x & 15, ty = threadIdx.x >> 4;  // cols e=tx*4+j, rows r=ty*2+i
    float acc[2][4];
    #pragma unroll
    for (int i = 0; i < 2; i++)
        #pragma unroll
        for (int j = 0; j < 4; j++) acc[i][j] = 0.f;
    float dsum[2] = {0.f, 0.f};

    const float* hbase   = g_h   + (size_t)h * NN * DD;
    const float* simbase = g_sim + (size_t)h * NN * NN;

    for (int cb = 0; cb < NN; cb += 128) {
        __syncthreads();
        // p-phase: keep rule + exp into sP
        #pragma unroll
        for (int t = 0; t < 4; t++) {
            int idx = threadIdx.x + t * 256;   // 0..1023 float4 slots
            int r = idx >> 5;
            int c = (idx & 31) << 2;
            size_t go = (size_t)(rb + r) * NN + cb + c;
            float4 s4 = *(const float4*)&simbase[go];
            int4   a4 = *(const int4*)&adj[go];
            float rm = sRM[r];
            float th = 0.5f * rm;
            float4 p;
            p.x = (a4.x > 0 && s4.x >= th) ? __expf(s4.x - rm) : 0.f;
            p.y = (a4.y > 0 && s4.y >= th) ? __expf(s4.y - rm) : 0.f;
            p.z = (a4.z > 0 && s4.z >= th) ? __expf(s4.z - rm) : 0.f;
            p.w = (a4.w > 0 && s4.w >= th) ? __expf(s4.w - rm) : 0.f;
            *(float4*)&sP[r * SP_STRIDE + c] = p;
        }
        // load h col-tile [128][64]
        #pragma unroll
        for (int t = 0; t < 8; t++) {
            int idx = threadIdx.x + t * 256;   // 0..2047 float4 slots
            int cc = idx >> 4;
            int e  = (idx & 15) << 2;
            *(float4*)&sHt[cc * DD + e] =
                *(const float4*)&hbase[(size_t)(cb + cc) * DD + e];
        }
        __syncthreads();
        #pragma unroll 4
        for (int k = 0; k < 128; k++) {
            float4 b = *(const float4*)&sHt[k * DD + tx * 4];
            float a0 = sP[(ty * 2 + 0) * SP_STRIDE + k];
            float a1 = sP[(ty * 2 + 1) * SP_STRIDE + k];
            acc[0][0] = fmaf(a0, b.x, acc[0][0]);
            acc[0][1] = fmaf(a0, b.y, acc[0][1]);
            acc[0][2] = fmaf(a0, b.z, acc[0][2]);
            acc[0][3] = fmaf(a0, b.w, acc[0][3]);
            acc[1][0] = fmaf(a1, b.x, acc[1][0]);
            acc[1][1] = fmaf(a1, b.y, acc[1][1]);
            acc[1][2] = fmaf(a1, b.z, acc[1][2]);
            acc[1][3] = fmaf(a1, b.w, acc[1][3]);
            if (tx == 0) { dsum[0] += a0; dsum[1] += a1; }
        }
    }
    __syncthreads();
    if (tx == 0) { sDen[ty * 2] = dsum[0]; sDen[ty * 2 + 1] = dsum[1]; }
    __syncthreads();

    #pragma unroll
    for (int i = 0; i < 2; i++) {
        int lr = ty * 2 + i;
        int r = rb + lr;
        float den = sDen[lr];
        #pragma unroll
        for (int j = 0; j < 4; j++) {
            int e = tx * 4 + j;
            // den==0 -> reference softmax over all-NEG row = uniform -> mean of h
            float v = (den > 0.f) ? (acc[i][j] / den) : g_hmean[h * DD + e];
            v = (v > 0.f) ? v : (expf(v) - 1.f);   // elu
            atomicAdd(&out[(size_t)r * DD + e], 0.25f * v);  // mean over 4 heads
        }
    }
}

// ---------------- launch ----------------
extern "C" void kernel_launch(void* const* d_in, const int* in_sizes, int n_in,
                              void* d_out, int out_size) {
    const float* feat = (const float*)d_in[0];
    const int*   adj  = (const int*)d_in[1];
    const float* Ws   = (const float*)d_in[2];
    float* out = (float*)d_out;

    const int simSmem  = 64 * 128 * 2 * (int)sizeof(float);                       // 64 KB
    const int attnSmem = (32 * SP_STRIDE + 128 * 64 + 32 + 32) * (int)sizeof(float);
    cudaFuncSetAttribute(k_sim,  cudaFuncAttributeMaxDynamicSharedMemorySize, simSmem);
    cudaFuncSetAttribute(k_attn, cudaFuncAttributeMaxDynamicSharedMemorySize, attnSmem);

    for (int s = 0; s < NSTEPS; s++) {
        k_init<<<1024, 256>>>(s, out);
        k_project<<<dim3(NN / 64, HH), 256>>>(s, feat, Ws);
        k_sim<<<dim3(NN / 128, NN / 128, HH), 256, simSmem>>>(s, adj);
        k_attn<<<dim3(NN / 32, HH), 256, attnSmem>>>(s, adj, out);
    }
}